// round 7
// baseline (speedup 1.0000x reference)
#include <cuda_runtime.h>
#include <cuda_fp16.h>
#include <cstdint>

// ---------------------------------------------------------------------------
// out[512, 65536] = inputs[512,256] @ features[65536,256]^T   (fp32 in/out)
//
// Toolchain: compute_103 virtual arch -> no tcgen05; tensor path is
// ldmatrix + mma.sync.m16n8k16 (HMMA, rt ~8 cyc/SMSP measured).
//
//  1) convert_kernel: fp32 -> fp16 streaming pass into __device__ globals.
//  2) gemm_kernel: 148 CTAs x 256 threads, CTA tile M=128 x N=128 x K=256,
//     B double-buffered 64KB tiles via cp.async (prefetch distance 2).
//     Warp tile 32x64 (4m x 2n warps). KEY CHANGE vs R6: all A fragments
//     (a_frag[16][2][4] = 128 regs) are loaded ONCE per CTA and kept
//     register-resident across the entire j-loop -- A-side ldmatrix traffic
//     (137KB/iter/SM) eliminated, smem crossbar no longer contends with the
//     HMMA stream. Epilogue uses streaming st.global.cs stores.
// ---------------------------------------------------------------------------

#define GY 37                       // grid.y; 4*37 = 148 CTAs (1/SM)
#define BLOCK 256
#define SMEM_BYTES (3 * 65536)      // A 64KB + B double buffer 2x64KB

__device__ __align__(256) __half g_fB[65536 * 256];  // features fp16
__device__ __align__(256) __half g_fA[512 * 256];    // inputs fp16

// ---------------- convert: fp32 -> fp16 streaming ----------------
__global__ void __launch_bounds__(256) convert_kernel(
    const float* __restrict__ features, const float* __restrict__ inputs)
{
    const int stride = gridDim.x * blockDim.x;
    const float4* f4 = reinterpret_cast<const float4*>(features);
    uint2* b4 = reinterpret_cast<uint2*>(g_fB);
    for (int i = blockIdx.x * blockDim.x + threadIdx.x; i < 4194304; i += stride) {
        float4 v = f4[i];
        __half2 h0 = __floats2half2_rn(v.x, v.y);
        __half2 h1 = __floats2half2_rn(v.z, v.w);
        b4[i] = make_uint2(*reinterpret_cast<uint32_t*>(&h0),
                           *reinterpret_cast<uint32_t*>(&h1));
    }
    const float4* i4 = reinterpret_cast<const float4*>(inputs);
    uint2* a4 = reinterpret_cast<uint2*>(g_fA);
    for (int i = blockIdx.x * blockDim.x + threadIdx.x; i < 32768; i += stride) {
        float4 v = i4[i];
        __half2 h0 = __floats2half2_rn(v.x, v.y);
        __half2 h1 = __floats2half2_rn(v.z, v.w);
        a4[i] = make_uint2(*reinterpret_cast<uint32_t*>(&h0),
                           *reinterpret_cast<uint32_t*>(&h1));
    }
}

// ---------------- gemm helpers ----------------
__device__ __forceinline__ uint32_t smem_u32(const void* p) {
    uint32_t a;
    asm("{ .reg .u64 t; cvta.to.shared.u64 t, %1; cvt.u32.u64 %0, t; }"
        : "=r"(a) : "l"(p));
    return a;
}

// Row = 512B (256 halves). Swizzle: XOR 16B-chunk index with (row & 7).
__device__ __forceinline__ uint32_t swz(uint32_t off) {
    return off ^ (((off >> 9) & 7u) << 4);
}

__device__ __forceinline__ void cp16(uint32_t dst, const void* src) {
    asm volatile("cp.async.cg.shared.global [%0], [%1], 16;"
                 :: "r"(dst), "l"(src));
}

__device__ __forceinline__ void ldm_x4(uint32_t* r, uint32_t addr) {
    asm volatile(
        "ldmatrix.sync.aligned.m8n8.x4.shared.b16 {%0,%1,%2,%3}, [%4];"
        : "=r"(r[0]), "=r"(r[1]), "=r"(r[2]), "=r"(r[3]) : "r"(addr));
}

__device__ __forceinline__ void mma_16816(float* c, const uint32_t* a,
                                          uint32_t b0, uint32_t b1) {
    asm volatile(
        "mma.sync.aligned.m16n8k16.row.col.f32.f16.f16.f32 "
        "{%0,%1,%2,%3}, {%4,%5,%6,%7}, {%8,%9}, {%0,%1,%2,%3};"
        : "+f"(c[0]), "+f"(c[1]), "+f"(c[2]), "+f"(c[3])
        : "r"(a[0]), "r"(a[1]), "r"(a[2]), "r"(a[3]), "r"(b0), "r"(b1));
}

__device__ __forceinline__ void stg_cs_v2(float* p, float x, float y) {
    asm volatile("st.global.cs.v2.f32 [%0], {%1, %2};"
                 :: "l"(p), "f"(x), "f"(y) : "memory");
}

// Issue cp.async for a full 128x256-half tile (64KB) into swizzled smem.
__device__ __forceinline__ void issue_tile_copy(uint32_t sdst,
                                                const __half* gsrc, int tid) {
#pragma unroll
    for (int q = tid; q < 4096; q += BLOCK) {
        int row = q >> 5;        // 32 x 16B chunks per 512B row
        int c   = q & 31;
        cp16(sdst + swz((uint32_t)(row * 512 + c * 16)),
             gsrc + row * 256 + c * 8);
    }
}

__global__ void __launch_bounds__(BLOCK, 1) gemm_kernel(float* __restrict__ out)
{
    extern __shared__ char smem[];
    const uint32_t sA  = smem_u32(smem);       // 128 x 512B
    const uint32_t sB0 = sA + 65536u;
    const uint32_t sB1 = sA + 131072u;

    const int tid = threadIdx.x;
    const int wid = tid >> 5;
    const int lid = tid & 31;
    const int wm = wid >> 1;    // 0..3  (32 m-rows each)
    const int wn = wid & 1;     // 0..1  (64 n-rows each)
    const int m_super = blockIdx.x;   // 0..3  (rows m_super*128 .. +128)
    const int j0 = blockIdx.y;        // first n-block; stride GY

    // Prologue: A tile + first two B tiles in flight (3 commit groups).
    issue_tile_copy(sA, g_fA + m_super * 128 * 256, tid);
    asm volatile("cp.async.commit_group;");
    issue_tile_copy(sB0, g_fB + (size_t)j0 * 128 * 256, tid);
    asm volatile("cp.async.commit_group;");
    issue_tile_copy(sB1, g_fB + (size_t)(j0 + GY) * 128 * 256, tid);
    asm volatile("cp.async.commit_group;");

    // Per-lane ldmatrix address components
    const int a_row = lid & 15;
    const int a_kb  = (lid >> 4) * 16;                 // bytes
    const int b_row = (lid & 7) + ((lid >> 4) * 8);
    const int b_kb  = ((lid >> 3) & 1) * 16;           // bytes

    // ---- Load ALL A fragments once; keep register-resident for the j-loop.
    asm volatile("cp.async.wait_group 2;");   // A tile complete
    __syncthreads();
    uint32_t a_frag[16][2][4];
#pragma unroll
    for (int ks = 0; ks < 16; ++ks) {
#pragma unroll
        for (int mf = 0; mf < 2; ++mf) {
            int row = wm * 32 + mf * 16 + a_row;
            ldm_x4(a_frag[ks][mf],
                   sA + swz((uint32_t)(row * 512) + (uint32_t)ks * 32 + a_kb));
        }
    }

    int parity = 0;
    for (int j = j0; j < 512; j += GY) {
        asm volatile("cp.async.wait_group 1;");
        __syncthreads();
        const uint32_t sB = parity ? sB1 : sB0;

        float acc[2][8][4];
#pragma unroll
        for (int mf = 0; mf < 2; ++mf)
#pragma unroll
            for (int nf = 0; nf < 8; ++nf)
#pragma unroll
                for (int e = 0; e < 4; ++e) acc[mf][nf][e] = 0.0f;

#pragma unroll
        for (int ks = 0; ks < 16; ++ks) {
            const uint32_t kb = (uint32_t)ks * 32;
            uint32_t b[4][4];
#pragma unroll
            for (int ng = 0; ng < 4; ++ng) {
                int nrow = wn * 64 + ng * 16 + b_row;
                ldm_x4(b[ng], sB + swz((uint32_t)(nrow * 512) + kb + b_kb));
            }
#pragma unroll
            for (int mf = 0; mf < 2; ++mf)
#pragma unroll
                for (int nf = 0; nf < 8; ++nf)
                    mma_16816(acc[mf][nf], a_frag[ks][mf],
                              b[nf >> 1][(nf & 1) * 2 + 0],
                              b[nf >> 1][(nf & 1) * 2 + 1]);
        }

        __syncthreads();   // all warps done reading sB(parity)

        // Prefetch B tile j + 2*GY into the freed buffer; overlaps epilogue
        // stores and the next iteration's MMA.
        int pf = j + 2 * GY;
        if (pf < 512)
            issue_tile_copy(parity ? sB1 : sB0,
                            g_fB + (size_t)pf * 128 * 256, tid);
        asm volatile("cp.async.commit_group;");

        // Epilogue: streaming GMEM float2 stores
        const int row0 = m_super * 128 + wm * 32 + (lid >> 2);
        const int col0 = j * 128 + wn * 64 + (lid & 3) * 2;
#pragma unroll
        for (int mf = 0; mf < 2; ++mf) {
#pragma unroll
            for (int nf = 0; nf < 8; ++nf) {
                const int r = row0 + mf * 16;
                const int c = col0 + nf * 8;
                stg_cs_v2(out + (size_t)r * 65536 + c,
                          acc[mf][nf][0], acc[mf][nf][1]);
                stg_cs_v2(out + (size_t)(r + 8) * 65536 + c,
                          acc[mf][nf][2], acc[mf][nf][3]);
            }
        }
        parity ^= 1;
    }
}

extern "C" void kernel_launch(void* const* d_in, const int* in_sizes, int n_in,
                              void* d_out, int out_size) {
    // metadata order: inputs f32[512,256], indexes i64[512],
    //                 features f32[65536,256], mIoU f32[65536], IoU f32[512];
    //                 output f32[512,65536]
    const float* inputs   = (const float*)d_in[0];
    const float* features = (const float*)d_in[2];
    float* out = (float*)d_out;

    convert_kernel<<<1184, 256>>>(features, inputs);

    cudaFuncSetAttribute(gemm_kernel,
                         cudaFuncAttributeMaxDynamicSharedMemorySize, SMEM_BYTES);
    // grid.x = m_super (fast): the 4 CTAs sharing each B tile run concurrently
    gemm_kernel<<<dim3(4, GY), BLOCK, SMEM_BYTES>>>(out);
}

// round 8
// speedup vs baseline: 1.0477x; 1.0477x over previous
#include <cuda_runtime.h>
#include <cuda_fp16.h>
#include <cstdint>

// ---------------------------------------------------------------------------
// out[512, 65536] = inputs[512,256] @ features[65536,256]^T   (fp32 in/out)
//
// Toolchain: compute_103 virtual arch -> no tcgen05; tensor path is
// ldmatrix + mma.sync.m16n8k16 (HMMA).
//
//  1) convert_kernel: fp32 -> fp16 streaming pass into __device__ globals.
//  2) gemm_kernel: 148 CTAs x 256 threads. PING-PONG: the CTA is split into
//     two independent 128-thread halves. Each half owns a private
//     double-buffered B stream (2 x 32KB, N=64 tiles, cp.async) and syncs
//     only itself via named barriers (bar.sync id,128). A (64KB, M=128) is
//     shared read-only. The halves run phase-shifted, so one half's MMA
//     burst covers the other half's barrier/wait/epilogue dead time --
//     attacking the lockstep idling that pinned tensor util at ~47%.
//     Warp tile 64x32 (R3's best-measured shape).
// ---------------------------------------------------------------------------

#define GY 37                            // grid (4, 37) = 148 CTAs (1/SM)
#define BLOCK 256
#define SMEM_BYTES (65536 + 4 * 32768)   // A 64KB + 2 halves x 2 x 32KB

__device__ __align__(256) __half g_fB[65536 * 256];  // features fp16
__device__ __align__(256) __half g_fA[512 * 256];    // inputs fp16

// ---------------- convert: fp32 -> fp16 streaming ----------------
__global__ void __launch_bounds__(256) convert_kernel(
    const float* __restrict__ features, const float* __restrict__ inputs)
{
    const int stride = gridDim.x * blockDim.x;
    const float4* f4 = reinterpret_cast<const float4*>(features);
    uint2* b4 = reinterpret_cast<uint2*>(g_fB);
    for (int i = blockIdx.x * blockDim.x + threadIdx.x; i < 4194304; i += stride) {
        float4 v = f4[i];
        __half2 h0 = __floats2half2_rn(v.x, v.y);
        __half2 h1 = __floats2half2_rn(v.z, v.w);
        b4[i] = make_uint2(*reinterpret_cast<uint32_t*>(&h0),
                           *reinterpret_cast<uint32_t*>(&h1));
    }
    const float4* i4 = reinterpret_cast<const float4*>(inputs);
    uint2* a4 = reinterpret_cast<uint2*>(g_fA);
    for (int i = blockIdx.x * blockDim.x + threadIdx.x; i < 32768; i += stride) {
        float4 v = i4[i];
        __half2 h0 = __floats2half2_rn(v.x, v.y);
        __half2 h1 = __floats2half2_rn(v.z, v.w);
        a4[i] = make_uint2(*reinterpret_cast<uint32_t*>(&h0),
                           *reinterpret_cast<uint32_t*>(&h1));
    }
}

// ---------------- gemm helpers ----------------
__device__ __forceinline__ uint32_t smem_u32(const void* p) {
    uint32_t a;
    asm("{ .reg .u64 t; cvta.to.shared.u64 t, %1; cvt.u32.u64 %0, t; }"
        : "=r"(a) : "l"(p));
    return a;
}

// Rows are 512B (256 halves). Swizzle: XOR 16B-chunk index with (row & 7).
__device__ __forceinline__ uint32_t swz(uint32_t off) {
    return off ^ (((off >> 9) & 7u) << 4);
}

__device__ __forceinline__ void cp16(uint32_t dst, const void* src) {
    asm volatile("cp.async.cg.shared.global [%0], [%1], 16;"
                 :: "r"(dst), "l"(src));
}

__device__ __forceinline__ void ldm_x4(uint32_t* r, uint32_t addr) {
    asm volatile(
        "ldmatrix.sync.aligned.m8n8.x4.shared.b16 {%0,%1,%2,%3}, [%4];"
        : "=r"(r[0]), "=r"(r[1]), "=r"(r[2]), "=r"(r[3]) : "r"(addr));
}

__device__ __forceinline__ void mma_16816(float* c, const uint32_t* a,
                                          uint32_t b0, uint32_t b1) {
    asm volatile(
        "mma.sync.aligned.m16n8k16.row.col.f32.f16.f16.f32 "
        "{%0,%1,%2,%3}, {%4,%5,%6,%7}, {%8,%9}, {%0,%1,%2,%3};"
        : "+f"(c[0]), "+f"(c[1]), "+f"(c[2]), "+f"(c[3])
        : "r"(a[0]), "r"(a[1]), "r"(a[2]), "r"(a[3]), "r"(b0), "r"(b1));
}

__device__ __forceinline__ void stg_cs_v2(float* p, float x, float y) {
    asm volatile("st.global.cs.v2.f32 [%0], {%1, %2};"
                 :: "l"(p), "f"(x), "f"(y) : "memory");
}

// A tile: 128 rows x 256 halves (64KB); issued by all 256 threads.
__device__ __forceinline__ void issue_A(uint32_t sA, const __half* g, int tid) {
#pragma unroll
    for (int q = tid; q < 4096; q += BLOCK) {
        int row = q >> 5;               // 32 x 16B chunks per 512B row
        int c   = q & 31;
        cp16(sA + swz((uint32_t)(row * 512 + c * 16)), g + row * 256 + c * 8);
    }
}

// B slab: 64 n-rows x 256 halves (32KB); issued by one 128-thread half.
__device__ __forceinline__ void issue_B(uint32_t sB, const __half* g, int htid) {
#pragma unroll
    for (int q = htid; q < 2048; q += 128) {
        int row = q >> 5;
        int c   = q & 31;
        cp16(sB + swz((uint32_t)(row * 512 + c * 16)), g + row * 256 + c * 8);
    }
}

__global__ void __launch_bounds__(BLOCK, 1) gemm_kernel(float* __restrict__ out)
{
    extern __shared__ char smem[];
    const uint32_t sA = smem_u32(smem);                 // 64KB shared A

    const int tid  = threadIdx.x;
    const int wid  = tid >> 5;
    const int lid  = tid & 31;
    const int half = wid >> 2;          // 0 or 1
    const int hw   = wid & 3;           // warp within half
    const int htid = tid & 127;
    const int wm   = hw >> 1;           // 0..1 (64 m-rows)
    const int wn   = hw & 1;            // 0..1 (32 n-rows)
    const int m_super = blockIdx.x;     // 0..3
    // n-block (64-wide) stream for this half: jb0 + i*74, jb < 1024
    const int jb0 = blockIdx.y * 2 + half;

    const uint32_t sBh = sA + 65536u + (uint32_t)half * 65536u;  // 2x32KB

    // Prologue: A (all threads) + this half's first two B slabs.
    issue_A(sA, g_fA + m_super * 128 * 256, tid);
    asm volatile("cp.async.commit_group;");
    issue_B(sBh, g_fB + (size_t)jb0 * 64 * 256, htid);
    asm volatile("cp.async.commit_group;");
    if (jb0 + 74 < 1024)
        issue_B(sBh + 32768u, g_fB + (size_t)(jb0 + 74) * 64 * 256, htid);
    asm volatile("cp.async.commit_group;");

    asm volatile("cp.async.wait_group 2;");   // A complete (this thread)
    __syncthreads();                          // A visible CTA-wide

    // Per-lane ldmatrix address components
    const int a_row = lid & 15;
    const int a_kb  = (lid >> 4) * 16;
    const int b_row = (lid & 7) + ((lid >> 4) * 8);
    const int b_kb  = ((lid >> 3) & 1) * 16;
    const int bar_id = 1 + half;

    int parity = 0;
    for (int jb = jb0; jb < 1024; jb += 74) {
        asm volatile("cp.async.wait_group 1;");
        asm volatile("bar.sync %0, 128;" :: "r"(bar_id) : "memory");
        const uint32_t sB = sBh + (uint32_t)parity * 32768u;

        float acc[4][4][4];
#pragma unroll
        for (int mf = 0; mf < 4; ++mf)
#pragma unroll
            for (int nf = 0; nf < 4; ++nf)
#pragma unroll
                for (int e = 0; e < 4; ++e) acc[mf][nf][e] = 0.0f;

#pragma unroll
        for (int ks = 0; ks < 16; ++ks) {
            const uint32_t kb = (uint32_t)ks * 32;
            uint32_t a[4][4];
#pragma unroll
            for (int mf = 0; mf < 4; ++mf) {
                int row = wm * 64 + mf * 16 + a_row;
                ldm_x4(a[mf], sA + swz((uint32_t)(row * 512) + kb + a_kb));
            }
            uint32_t b[2][4];
#pragma unroll
            for (int ng = 0; ng < 2; ++ng) {
                int nrow = wn * 32 + ng * 16 + b_row;
                ldm_x4(b[ng], sB + swz((uint32_t)(nrow * 512) + kb + b_kb));
            }
#pragma unroll
            for (int mf = 0; mf < 4; ++mf)
#pragma unroll
                for (int nf = 0; nf < 4; ++nf)
                    mma_16816(acc[mf][nf], a[mf],
                              b[nf >> 1][(nf & 1) * 2 + 0],
                              b[nf >> 1][(nf & 1) * 2 + 1]);
        }

        asm volatile("bar.sync %0, 128;" :: "r"(bar_id) : "memory");

        // Prefetch slab jb+148 into the buffer this half just finished.
        if (jb + 148 < 1024)
            issue_B(sB, g_fB + (size_t)(jb + 148) * 64 * 256, htid);
        asm volatile("cp.async.commit_group;");

        // Epilogue: streaming GMEM float2 stores
        const int row0 = m_super * 128 + wm * 64 + (lid >> 2);
        const int col0 = jb * 64 + wn * 32 + (lid & 3) * 2;
#pragma unroll
        for (int mf = 0; mf < 4; ++mf) {
#pragma unroll
            for (int nf = 0; nf < 4; ++nf) {
                const int r = row0 + mf * 16;
                const int c = col0 + nf * 8;
                stg_cs_v2(out + (size_t)r * 65536 + c,
                          acc[mf][nf][0], acc[mf][nf][1]);
                stg_cs_v2(out + (size_t)(r + 8) * 65536 + c,
                          acc[mf][nf][2], acc[mf][nf][3]);
            }
        }
        parity ^= 1;
    }
}

extern "C" void kernel_launch(void* const* d_in, const int* in_sizes, int n_in,
                              void* d_out, int out_size) {
    // metadata order: inputs f32[512,256], indexes i64[512],
    //                 features f32[65536,256], mIoU f32[65536], IoU f32[512];
    //                 output f32[512,65536]
    const float* inputs   = (const float*)d_in[0];
    const float* features = (const float*)d_in[2];
    float* out = (float*)d_out;

    convert_kernel<<<1184, 256>>>(features, inputs);

    cudaFuncSetAttribute(gemm_kernel,
                         cudaFuncAttributeMaxDynamicSharedMemorySize, SMEM_BYTES);
    // grid.x = m_super (fast): the 4 CTAs sharing each B slab run concurrently
    gemm_kernel<<<dim3(4, GY), BLOCK, SMEM_BYTES>>>(out);
}

// round 9
// speedup vs baseline: 1.0703x; 1.0216x over previous
#include <cuda_runtime.h>
#include <cuda_fp16.h>
#include <cstdint>

// ---------------------------------------------------------------------------
// out[512, 65536] = inputs[512,256] @ features[65536,256]^T   (fp32 in/out)
//
// Toolchain: compute_103 virtual arch -> no tcgen05; tensor path is
// ldmatrix + mma.sync.m16n8k16 (HMMA). Measured across 5 schedules: the
// f32-accum HMMA pipe saturates at ~48% counter (= mma.sync roofline on
// sm_103a); gemm mainloop ~59us is the floor. This round removes the
// separate fp32->fp16 convert kernel (~17us) by fusing conversion into the
// gemm: B slabs are LDG'd as fp32 into registers (2 batches of 16 float4,
// issued at ks0/ks8, consumed at ks7/ks15), converted, and STS'd fp16 into
// the ping-pong smem buffers. The 4 m_super CTAs read each fp32 slab
// concurrently (1 DRAM miss + 3 L2 hits; B fp32 = 64MB fits L2). A is
// converted in the prologue. Single kernel, single launch.
//
// Structure: 148 CTAs x 256 threads, two independent 128-thread halves
// (ping-pong, named barriers), each half streams N=64 B slabs, warp tile
// 64x32, K=256 smem-resident A.
// ---------------------------------------------------------------------------

#define GY 37                            // grid (4, 37) = 148 CTAs (1/SM)
#define BLOCK 256
#define SMEM_BYTES (65536 + 4 * 32768)   // A 64KB + 2 halves x 2 x 32KB fp16

__device__ __forceinline__ uint32_t smem_u32(const void* p) {
    uint32_t a;
    asm("{ .reg .u64 t; cvta.to.shared.u64 t, %1; cvt.u32.u64 %0, t; }"
        : "=r"(a) : "l"(p));
    return a;
}

// Rows are 512B (256 halves). Swizzle: XOR 16B-chunk index with (row & 7).
__device__ __forceinline__ uint32_t swz(uint32_t off) {
    return off ^ (((off >> 9) & 7u) << 4);
}

__device__ __forceinline__ void ldm_x4(uint32_t* r, uint32_t addr) {
    asm volatile(
        "ldmatrix.sync.aligned.m8n8.x4.shared.b16 {%0,%1,%2,%3}, [%4];"
        : "=r"(r[0]), "=r"(r[1]), "=r"(r[2]), "=r"(r[3]) : "r"(addr));
}

__device__ __forceinline__ void mma_16816(float* c, const uint32_t* a,
                                          uint32_t b0, uint32_t b1) {
    asm volatile(
        "mma.sync.aligned.m16n8k16.row.col.f32.f16.f16.f32 "
        "{%0,%1,%2,%3}, {%4,%5,%6,%7}, {%8,%9}, {%0,%1,%2,%3};"
        : "+f"(c[0]), "+f"(c[1]), "+f"(c[2]), "+f"(c[3])
        : "r"(a[0]), "r"(a[1]), "r"(a[2]), "r"(a[3]), "r"(b0), "r"(b1));
}

__device__ __forceinline__ void stg_cs_v2(float* p, float x, float y) {
    asm volatile("st.global.cs.v2.f32 [%0], {%1, %2};"
                 :: "l"(p), "f"(x), "f"(y) : "memory");
}

// Convert one float4 to 4 halves and store 8B to swizzled smem.
__device__ __forceinline__ void cvt_sts(uint32_t smem_addr, float4 v) {
    __half2 h0 = __floats2half2_rn(v.x, v.y);
    __half2 h1 = __floats2half2_rn(v.z, v.w);
    asm volatile("st.shared.v2.b32 [%0], {%1, %2};"
                 :: "r"(smem_addr),
                    "r"(*reinterpret_cast<uint32_t*>(&h0)),
                    "r"(*reinterpret_cast<uint32_t*>(&h1)));
}

__global__ void __launch_bounds__(BLOCK, 1) gemm_kernel(
    const float* __restrict__ inputs,    // [512, 256]
    const float* __restrict__ features,  // [65536, 256]
    float* __restrict__ out)             // [512, 65536]
{
    extern __shared__ char smem[];
    const uint32_t sA = smem_u32(smem);                 // 64KB shared A fp16

    const int tid  = threadIdx.x;
    const int wid  = tid >> 5;
    const int lid  = tid & 31;
    const int half = wid >> 2;          // 0 or 1
    const int hw   = wid & 3;           // warp within half
    const int htid = tid & 127;
    const int wm   = hw >> 1;           // 0..1 (64 m-rows)
    const int wn   = hw & 1;            // 0..1 (32 n-rows)
    const int m_super = blockIdx.x;     // 0..3
    const int jb0 = blockIdx.y * 2 + half;   // slab stream: jb0 + k*74 < 1024

    const uint32_t sBh = sA + 65536u + (uint32_t)half * 65536u;  // 2x32KB

    // ---- Prologue: convert A stripe fp32 -> fp16 smem (whole CTA) ----
    {
        const float4* Ag = reinterpret_cast<const float4*>(inputs)
                         + m_super * 8192;
#pragma unroll 8
        for (int it = 0; it < 32; ++it) {
            int fi = it * 256 + tid;           // coalesced
            float4 v = __ldg(Ag + fi);
            int row = fi >> 6;                 // 64 float4 per 256-half row
            int c4  = fi & 63;
            cvt_sts(sA + swz((uint32_t)(row * 512 + c4 * 8)), v);
        }
    }
    // ---- Prologue: convert this half's first B slab into buffer 0 ----
    {
        const float4* Bg = reinterpret_cast<const float4*>(features)
                         + (size_t)jb0 * 4096;
#pragma unroll 8
        for (int it = 0; it < 32; ++it) {
            int fi = it * 128 + htid;
            float4 v = __ldg(Bg + fi);
            int row = fi >> 6;
            int c4  = fi & 63;
            cvt_sts(sBh + swz((uint32_t)(row * 512 + c4 * 8)), v);
        }
    }
    __syncthreads();   // A visible CTA-wide; each half's slab 0 in place

    // Per-lane ldmatrix address components
    const int a_row = lid & 15;
    const int a_kb  = (lid >> 4) * 16;
    const int b_row = (lid & 7) + ((lid >> 4) * 8);
    const int b_kb  = ((lid >> 3) & 1) * 16;
    const int bar_id = 1 + half;
    // Per-thread STS placement for converted B batches:
    //   batch r covers it = batch*16 + r; row = it*2 + (htid>>6), c4 = htid&63
    const int srow = htid >> 6;          // 0..1
    const int sc4  = htid & 63;

    int parity = 0;
    for (int jb = jb0; jb < 1024; jb += 74) {
        const bool has_nxt = (jb + 74) < 1024;
        const float4* src = reinterpret_cast<const float4*>(features)
                          + (size_t)(jb + 74) * 4096;
        const uint32_t sBc = sBh + (uint32_t)parity * 32768u;        // compute
        const uint32_t sBn = sBh + (uint32_t)(parity ^ 1) * 32768u;  // fill

        float acc[4][4][4];
#pragma unroll
        for (int mf = 0; mf < 4; ++mf)
#pragma unroll
            for (int nf = 0; nf < 4; ++nf)
#pragma unroll
                for (int e = 0; e < 4; ++e) acc[mf][nf][e] = 0.0f;

        float4 stage[16];

#pragma unroll
        for (int ks = 0; ks < 16; ++ks) {
            // Issue fp32 LDG batches for the NEXT slab early; consume late.
            if (ks == 0 && has_nxt) {
#pragma unroll
                for (int r = 0; r < 16; ++r)
                    stage[r] = __ldg(src + r * 128 + htid);
            }
            if (ks == 8) {
                if (has_nxt) {
#pragma unroll
                    for (int r = 0; r < 16; ++r) {     // consume batch 0
                        int it = r;
                        uint32_t off = (uint32_t)((it * 2 + srow) * 512 + sc4 * 8);
                        cvt_sts(sBn + swz(off), stage[r]);
                    }
#pragma unroll
                    for (int r = 0; r < 16; ++r)       // issue batch 1
                        stage[r] = __ldg(src + (16 + r) * 128 + htid);
                }
            }

            const uint32_t kb = (uint32_t)ks * 32;
            uint32_t a[4][4];
#pragma unroll
            for (int mf = 0; mf < 4; ++mf) {
                int row = wm * 64 + mf * 16 + a_row;
                ldm_x4(a[mf], sA + swz((uint32_t)(row * 512) + kb + a_kb));
            }
            uint32_t b[2][4];
#pragma unroll
            for (int ng = 0; ng < 2; ++ng) {
                int nrow = wn * 32 + ng * 16 + b_row;
                ldm_x4(b[ng], sBc + swz((uint32_t)(nrow * 512) + kb + b_kb));
            }
#pragma unroll
            for (int mf = 0; mf < 4; ++mf)
#pragma unroll
                for (int nf = 0; nf < 4; ++nf)
                    mma_16816(acc[mf][nf], a[mf],
                              b[nf >> 1][(nf & 1) * 2 + 0],
                              b[nf >> 1][(nf & 1) * 2 + 1]);
        }

        // Consume batch 1 into the fill buffer.
        if (has_nxt) {
#pragma unroll
            for (int r = 0; r < 16; ++r) {
                int it = 16 + r;
                uint32_t off = (uint32_t)((it * 2 + srow) * 512 + sc4 * 8);
                cvt_sts(sBn + swz(off), stage[r]);
            }
        }

        // Epilogue: streaming GMEM float2 stores
        const int row0 = m_super * 128 + wm * 64 + (lid >> 2);
        const int col0 = jb * 64 + wn * 32 + (lid & 3) * 2;
#pragma unroll
        for (int mf = 0; mf < 4; ++mf) {
#pragma unroll
            for (int nf = 0; nf < 4; ++nf) {
                const int r = row0 + mf * 16;
                const int c = col0 + nf * 8;
                stg_cs_v2(out + (size_t)r * 65536 + c,
                          acc[mf][nf][0], acc[mf][nf][1]);
                stg_cs_v2(out + (size_t)(r + 8) * 65536 + c,
                          acc[mf][nf][2], acc[mf][nf][3]);
            }
        }

        // Half-local barrier: all 4 warps done reading sBc and writing sBn.
        asm volatile("bar.sync %0, 128;" :: "r"(bar_id) : "memory");
        parity ^= 1;
    }
}

extern "C" void kernel_launch(void* const* d_in, const int* in_sizes, int n_in,
                              void* d_out, int out_size) {
    // metadata order: inputs f32[512,256], indexes i64[512],
    //                 features f32[65536,256], mIoU f32[65536], IoU f32[512];
    //                 output f32[512,65536]
    const float* inputs   = (const float*)d_in[0];
    const float* features = (const float*)d_in[2];
    float* out = (float*)d_out;

    cudaFuncSetAttribute(gemm_kernel,
                         cudaFuncAttributeMaxDynamicSharedMemorySize, SMEM_BYTES);
    // grid.x = m_super (fast): the 4 CTAs sharing each B slab run concurrently
    gemm_kernel<<<dim3(4, GY), BLOCK, SMEM_BYTES>>>(inputs, features, out);
}